// round 15
// baseline (speedup 1.0000x reference)
#include <cuda_runtime.h>
#include <cuda_fp16.h>
#include <cstdint>

#define DCH 128
#define TMR 128
#define ROWB 272               // 256B data + 16B pad

#define OFF_A   0
#define OFF_B0  (128 * ROWB)
#define OFF_B1  (2 * 128 * ROWB)
#define OFF_PS  (3 * 128 * ROWB)
#define SMEM_SZ (OFF_PS + 2048 + 64)

#define SLAB_B  (128 * 256)

// counters: 0=ACC0 1=P0(qc+nc0) 2=ACC1 3=P1(qc L1) 4=EDGE1
__device__ int g_cnt[8];

// ---------------- scratch (alloc-free) ----------------
__device__ float g_qc[4000 * 128];
__device__ float g_nc0[20000 * 128];
__device__ float g_nc1[20000 * 128];
__device__ float g_acc[4000 * 128];
__device__ float g_agts[4000 * 128];
__device__ __align__(16) unsigned char g_wp[2 * 8 * SLAB_B];

// slabs: 0=Wq 1=Wc1a 2=Wc1b 3=Wc1c 4=Wc2 5=Wa 6=Wl 7=Wd2

struct P {
  const float* agts; const float* nodes;
  const float* actor_ctrs; const float* node_ctrs;
  const int* hi; const int* wi;
  const unsigned char* wp; const unsigned char* wpPrev;
  const float* Wd1; const float* bd1;
  const float *gnq_w, *gnq_b, *gnd2_w, *gnd2_b, *gnc1_w, *gnc1_b,
              *gnn_w, *gnn_b, *gnl_w, *gnl_b;
  const float *gnn0_w, *gnn0_b, *gnl0_w, *gnl0_b;
  const float* res;
  float *qc, *nc, *nc1, *acc, *agts1, *out;
  int M, N, E, mb, nb, eb;
  int cP, tP, cA, sigE;
};

__device__ __forceinline__ uint32_t smem_u32(const void* p) {
  uint32_t a;
  asm("{ .reg .u64 t; cvta.to.shared.u64 t, %1; cvt.u32.u64 %0, t; }" : "=r"(a) : "l"(p));
  return a;
}
#define LDSM4(r0, r1, r2, r3, addr) \
  asm volatile("ldmatrix.sync.aligned.m8n8.x4.shared.b16 {%0,%1,%2,%3}, [%4];" \
    : "=r"(r0), "=r"(r1), "=r"(r2), "=r"(r3) : "r"(addr))
#define STS32(addr, v) \
  asm volatile("st.shared.u32 [%0], %1;" :: "r"(addr), "r"(v))
#define CP_A16(dst, src) \
  asm volatile("cp.async.cg.shared.global [%0], [%1], 16;" :: "r"(dst), "l"(src))
#define CP_COMMIT() asm volatile("cp.async.commit_group;" ::: "memory")
#define CP_WAIT(n)  asm volatile("cp.async.wait_group %0;" :: "n"(n) : "memory")
#define REDV2(ptr, x, y) \
  asm volatile("red.global.v2.f32.add [%0], {%1, %2};" :: "l"(ptr), "f"(x), "f"(y) : "memory")
#define PREF_L2(ptr) asm volatile("prefetch.global.L2 [%0];" :: "l"(ptr))

__device__ __forceinline__ void signal_cnt(int idx) {
  __syncthreads();
  __threadfence();
  if (threadIdx.x == 0) atomicAdd(&g_cnt[idx], 1);
}
__device__ __forceinline__ void wait_cnt(int idx, int target) {
  if (threadIdx.x == 0) {
    while (atomicAdd(&g_cnt[idx], 0) < target) __nanosleep(128);
    __threadfence();
  }
  __syncthreads();
}

__device__ __forceinline__ uint32_t h2pack(float lo, float hi) {
  uint32_t r;
  asm("cvt.rn.f16x2.f32 %0, %1, %2;" : "=r"(r) : "f"(hi), "f"(lo));
  return r;
}

__device__ __forceinline__ void mma_h(float c[4], const uint32_t a[4],
                                      uint32_t b0, uint32_t b1) {
  asm volatile(
    "mma.sync.aligned.m16n8k16.row.col.f32.f16.f16.f32 "
    "{%0,%1,%2,%3}, {%4,%5,%6,%7}, {%8,%9}, {%0,%1,%2,%3};"
    : "+f"(c[0]), "+f"(c[1]), "+f"(c[2]), "+f"(c[3])
    : "r"(a[0]), "r"(a[1]), "r"(a[2]), "r"(a[3]), "r"(b0), "r"(b1));
}

__device__ __forceinline__ void store_A_h(char* smem, const float v[32], int r, int q) {
  char* rowp = smem + OFF_A + r * ROWB + q * 64;
#pragma unroll
  for (int a = 0; a < 4; a++) {
    uint4 o = make_uint4(h2pack(v[8 * a],     v[8 * a + 1]),
                         h2pack(v[8 * a + 2], v[8 * a + 3]),
                         h2pack(v[8 * a + 4], v[8 * a + 5]),
                         h2pack(v[8 * a + 6], v[8 * a + 7]));
    *(uint4*)(rowp + a * 16) = o;
  }
}

__device__ __forceinline__ void copy_B_async(char* smem, int bOff, const unsigned char* wps) {
  const uint32_t dst = smem_u32(smem) + bOff;
  for (int i = threadIdx.x; i < 2048; i += 256) {
    int row = i >> 4, u = i & 15;
    CP_A16(dst + row * ROWB + u * 16, wps + (size_t)i * 16);
  }
  CP_COMMIT();
}

__device__ __forceinline__ void mainloop_h(const char* smem, int bOff, float acc[2][8][4],
                                           int rowb, int cwb, int lane) {
  const uint32_t Ab = smem_u32(smem) + OFF_A;
  const uint32_t Bb = smem_u32(smem) + bOff;
  const uint32_t aAddr = Ab + (rowb + (lane & 15)) * ROWB + ((lane >> 4) << 4);
  const uint32_t bAddr = Bb + (cwb + ((lane >> 4) << 3) + (lane & 7)) * ROWB
                            + ((lane & 8) ? 16 : 0);
#pragma unroll
  for (int ms = 0; ms < 2; ms++)
#pragma unroll
    for (int ns = 0; ns < 8; ns++)
#pragma unroll
      for (int q = 0; q < 4; q++) acc[ms][ns][q] = 0.f;
#pragma unroll
  for (int ks = 0; ks < 8; ks++) {
    uint32_t a[2][4], b[4][4];
    LDSM4(a[0][0], a[0][1], a[0][2], a[0][3], aAddr + ks * 32);
    LDSM4(a[1][0], a[1][1], a[1][2], a[1][3], aAddr + 16 * ROWB + ks * 32);
#pragma unroll
    for (int pr = 0; pr < 4; pr++)
      LDSM4(b[pr][0], b[pr][1], b[pr][2], b[pr][3], bAddr + pr * 16 * ROWB + ks * 32);
#pragma unroll
    for (int ns = 0; ns < 8; ns++) {
      uint32_t b0 = b[ns >> 1][(ns & 1) * 2], b1 = b[ns >> 1][(ns & 1) * 2 + 1];
      mma_h(acc[0][ns], a[0], b0, b1);
      mma_h(acc[1][ns], a[1], b0, b1);
    }
  }
}

__device__ __forceinline__ void gn_ep(float f[2][8][4], char* smem,
                                      const float* gnw, const float* gnb,
                                      int rowb, int cwb, int nw, int g, int tg,
                                      bool dorelu) {
  float* ps = (float*)(smem + OFF_PS);
  float* pq = ps + 256;
#pragma unroll
  for (int ms = 0; ms < 2; ms++)
#pragma unroll
    for (int h = 0; h < 2; h++) {
      float s = 0.f, q = 0.f;
#pragma unroll
      for (int ns = 0; ns < 8; ns++)
#pragma unroll
        for (int j = 0; j < 2; j++) {
          float v = f[ms][ns][2 * h + j];
          s += v;
          q = fmaf(v, v, q);
        }
      s += __shfl_xor_sync(0xffffffffu, s, 1);
      q += __shfl_xor_sync(0xffffffffu, q, 1);
      s += __shfl_xor_sync(0xffffffffu, s, 2);
      q += __shfl_xor_sync(0xffffffffu, q, 2);
      const int r = rowb + ms * 16 + h * 8 + g;
      if (tg == 0) { ps[nw * 128 + r] = s; pq[nw * 128 + r] = q; }
    }
  __syncthreads();
  const int c0 = cwb + tg * 2;
#pragma unroll
  for (int ms = 0; ms < 2; ms++)
#pragma unroll
    for (int h = 0; h < 2; h++) {
      const int r = rowb + ms * 16 + h * 8 + g;
      float s = ps[r] + ps[128 + r];
      float q = pq[r] + pq[128 + r];
      float m = s * (1.f / DCH);
      float var = q * (1.f / DCH) - m * m;
      float inv = rsqrtf(var + 1e-5f);
#pragma unroll
      for (int ns = 0; ns < 8; ns++) {
        float2 gw = *(const float2*)(gnw + c0 + ns * 8);
        float2 gb = *(const float2*)(gnb + c0 + ns * 8);
        float a0 = fmaf((f[ms][ns][2 * h]     - m) * inv, gw.x, gb.x);
        float a1 = fmaf((f[ms][ns][2 * h + 1] - m) * inv, gw.y, gb.y);
        if (dorelu) { a0 = fmaxf(a0, 0.f); a1 = fmaxf(a1, 0.f); }
        f[ms][ns][2 * h]     = a0;
        f[ms][ns][2 * h + 1] = a1;
      }
    }
}

__device__ __forceinline__ void repack_A(const float f[2][8][4], char* smem,
                                         int rowb, int cwb, int g, int tg) {
  const uint32_t Ab = smem_u32(smem) + OFF_A;
#pragma unroll
  for (int ms = 0; ms < 2; ms++)
#pragma unroll
    for (int h = 0; h < 2; h++) {
      const int r = rowb + ms * 16 + h * 8 + g;
#pragma unroll
      for (int ns = 0; ns < 8; ns++) {
        const int c = cwb + ns * 8 + tg * 2;
        STS32(Ab + r * ROWB + c * 2, h2pack(f[ms][ns][2 * h], f[ms][ns][2 * h + 1]));
      }
    }
}

__device__ __forceinline__ void store_plain(const float f[2][8][4], float* Y, int row0,
                                            int rows, int rowb, int cwb, int g, int tg) {
  const int c0 = cwb + tg * 2;
#pragma unroll
  for (int ms = 0; ms < 2; ms++)
#pragma unroll
    for (int h = 0; h < 2; h++) {
      const int gr = row0 + rowb + ms * 16 + h * 8 + g;
      if (gr < rows) {
        float* dst = Y + (size_t)gr * DCH + c0;
#pragma unroll
        for (int ns = 0; ns < 8; ns++)
          *(float2*)(dst + ns * 8) =
              make_float2(f[ms][ns][2 * h], f[ms][ns][2 * h + 1]);
      }
    }
}

__device__ __forceinline__ void load_A_h(char* smem, const float* X, int row0, int rows) {
  const int q = threadIdx.x & 3;
  for (int r = threadIdx.x >> 2; r < TMR; r += 64) {
    const int gr = row0 + r;
    const float* px = X + (size_t)gr * DCH + q * 32;
    float v[32];
#pragma unroll
    for (int i = 0; i < 8; i++) {
      float4 t = (gr < rows) ? *(const float4*)(px + 4 * i) : make_float4(0.f, 0.f, 0.f, 0.f);
      v[4 * i] = t.x; v[4 * i + 1] = t.y; v[4 * i + 2] = t.z; v[4 * i + 3] = t.w;
    }
    store_A_h(smem, v, r, q);
  }
}

// load A = relu(gn(X)) rows — L2-coherent reads (ld.cg: X mutated within this launch)
__device__ __forceinline__ void load_A_gn(char* smem, const float* X, int row0, int rows,
                                          const float* gnw, const float* gnb) {
  const int q = threadIdx.x & 3;
  for (int r = threadIdx.x >> 2; r < TMR; r += 64) {
    const int gr = row0 + r;
    float v[32];
    const float4* px = (const float4*)(X + (size_t)gr * DCH + q * 32);
#pragma unroll
    for (int i = 0; i < 8; i++) {
      float4 t = (gr < rows) ? __ldcg(px + i) : make_float4(0.f, 0.f, 0.f, 0.f);
      v[4 * i] = t.x; v[4 * i + 1] = t.y; v[4 * i + 2] = t.z; v[4 * i + 3] = t.w;
    }
    float s = 0.f, qq = 0.f;
#pragma unroll
    for (int i = 0; i < 32; i++) { s += v[i]; qq = fmaf(v[i], v[i], qq); }
    s  += __shfl_xor_sync(0xffffffffu, s, 1);
    qq += __shfl_xor_sync(0xffffffffu, qq, 1);
    s  += __shfl_xor_sync(0xffffffffu, s, 2);
    qq += __shfl_xor_sync(0xffffffffu, qq, 2);
    float m = s * (1.f / DCH);
    float var = qq * (1.f / DCH) - m * m;
    float inv = rsqrtf(var + 1e-5f);
#pragma unroll
    for (int i = 0; i < 32; i++) {
      const int c = q * 32 + i;
      v[i] = fmaxf(fmaf((v[i] - m) * inv, gnw[c], gnb[c]), 0.f);
    }
    store_A_h(smem, v, r, q);
  }
}

// ---------------- weight pack (+ counter reset each replay) ----------------
__global__ void wpack_kernel(const float* Wq, const float* Wc1, const float* Wc2,
                             const float* Wa, const float* Wl, const float* Wd2,
                             unsigned char* wp) {
  if (blockIdx.x == 0 && threadIdx.x < 8) g_cnt[threadIdx.x] = 0;
  int L = blockIdx.x >> 3, s = blockIdx.x & 7;
  const float* src;
  int ldw = DCH, coff = 0;
  switch (s) {
    case 0: src = Wq  + (size_t)L * DCH * DCH; break;
    case 1: src = Wc1 + (size_t)L * DCH * 3 * DCH; ldw = 3 * DCH; coff = 0;       break;
    case 2: src = Wc1 + (size_t)L * DCH * 3 * DCH; ldw = 3 * DCH; coff = DCH;     break;
    case 3: src = Wc1 + (size_t)L * DCH * 3 * DCH; ldw = 3 * DCH; coff = 2 * DCH; break;
    case 4: src = Wc2 + (size_t)L * DCH * DCH; break;
    case 5: src = Wa  + (size_t)L * DCH * DCH; break;
    case 6: src = Wl  + (size_t)L * DCH * DCH; break;
    default: src = Wd2 + (size_t)L * DCH * DCH; break;
  }
  unsigned char* dst = wp + (size_t)(L * 8 + s) * SLAB_B;
  const int j = threadIdx.x;
  const float* wr = src + (size_t)j * ldw + coff;
#pragma unroll
  for (int a = 0; a < 16; a++) {
    uint2 o = make_uint2(h2pack(wr[8 * a],     wr[8 * a + 1]),
                         h2pack(wr[8 * a + 2], wr[8 * a + 3]));
    uint2 o2 = make_uint2(h2pack(wr[8 * a + 4], wr[8 * a + 5]),
                          h2pack(wr[8 * a + 6], wr[8 * a + 7]));
    *(uint4*)(dst + (size_t)j * 256 + a * 16) = make_uint4(o.x, o.y, o2.x, o2.y);
  }
}

// ---------------- jobs ----------------
// agts-job (layer0): Wa->acc [sig ACC0], Wq->gn->repack, Wc1b->qc [sig P0]
__device__ void job_agts0(const P& p, int bid, char* smem,
                          int rowb, int cwb, int nw, int g, int tg, int lane) {
  const int row0 = bid * TMR;
  float f[2][8][4];
  copy_B_async(smem, OFF_B0, p.wp + 5 * SLAB_B);   // Wa   g0
  copy_B_async(smem, OFF_B1, p.wp + 0 * SLAB_B);   // Wq   g1
  load_A_h(smem, p.agts, row0, p.M);
  CP_WAIT(1);
  __syncthreads();
  mainloop_h(smem, OFF_B0, f, rowb, cwb, lane);
  store_plain(f, p.acc, row0, p.M, rowb, cwb, g, tg);
  signal_cnt(0);                                   // ACC0 ready (also syncs B0 reads)
  copy_B_async(smem, OFF_B0, p.wp + 2 * SLAB_B);   // Wc1b g2
  CP_WAIT(1);
  __syncthreads();
  mainloop_h(smem, OFF_B1, f, rowb, cwb, lane);
  gn_ep(f, smem, p.gnq_w, p.gnq_b, rowb, cwb, nw, g, tg, true);
  repack_A(f, smem, rowb, cwb, g, tg);
  CP_WAIT(0);
  __syncthreads();
  mainloop_h(smem, OFF_B0, f, rowb, cwb, lane);
  store_plain(f, p.qc, row0, p.M, rowb, cwb, g, tg);
  signal_cnt(1);                                   // P0 +1
}

// nodes-job: nc0 [sig P0], nc1
__device__ void job_nodes(const P& p, int bid, char* smem,
                          int rowb, int cwb, int nw, int g, int tg, int lane) {
  const int row0 = bid * TMR;
  float f[2][8][4];
  copy_B_async(smem, OFF_B0, p.wp + 3 * SLAB_B);       // Wc1c L0
  copy_B_async(smem, OFF_B1, p.wpPrev + 3 * SLAB_B);   // Wc1c L1
  load_A_h(smem, p.nodes, row0, p.N);
  CP_WAIT(1);
  __syncthreads();
  mainloop_h(smem, OFF_B0, f, rowb, cwb, lane);
  store_plain(f, p.nc, row0, p.N, rowb, cwb, g, tg);
  signal_cnt(1);                                       // P0 +1 (nc0 ready)
  CP_WAIT(0);
  __syncthreads();
  mainloop_h(smem, OFF_B1, f, rowb, cwb, lane);
  store_plain(f, p.nc1, row0, p.N, rowb, cwb, g, tg);
}

// mn1-job: f-recompute(L0)->agts1, Wa->acc [sig ACC1], Wq, Wc1b->qc [sig P1]
__device__ void job_mn1(const P& p, int bid, char* smem,
                        int rowb, int cwb, int nw, int g, int tg, int lane) {
  const int row0 = bid * TMR;
  float f[2][8][4];
  copy_B_async(smem, OFF_B0, p.wpPrev + 6 * SLAB_B);   // Wl(L0)  g0
  copy_B_async(smem, OFF_B1, p.wp + 5 * SLAB_B);       // Wa(L1)  g1
  load_A_gn(smem, p.acc, row0, p.M, p.gnn0_w, p.gnn0_b);
  CP_WAIT(1);
  __syncthreads();
  mainloop_h(smem, OFF_B0, f, rowb, cwb, lane);
  gn_ep(f, smem, p.gnl0_w, p.gnl0_b, rowb, cwb, nw, g, tg, false);
  {
    const int c0 = cwb + tg * 2;
#pragma unroll
    for (int ms = 0; ms < 2; ms++)
#pragma unroll
      for (int h = 0; h < 2; h++) {
        const int gr = row0 + rowb + ms * 16 + h * 8 + g;
        if (gr < p.M) {
          const float* rp = p.res + (size_t)gr * DCH + c0;
#pragma unroll
          for (int ns = 0; ns < 8; ns++) {
            float2 rv = *(const float2*)(rp + ns * 8);
            f[ms][ns][2 * h]     = fmaxf(f[ms][ns][2 * h]     + rv.x, 0.f);
            f[ms][ns][2 * h + 1] = fmaxf(f[ms][ns][2 * h + 1] + rv.y, 0.f);
          }
        } else {
#pragma unroll
          for (int ns = 0; ns < 8; ns++) {
            f[ms][ns][2 * h] = 0.f;
            f[ms][ns][2 * h + 1] = 0.f;
          }
        }
      }
  }
  store_plain(f, p.agts1, row0, p.M, rowb, cwb, g, tg);
  copy_B_async(smem, OFF_B0, p.wp + 0 * SLAB_B);       // Wq(L1) g2
  repack_A(f, smem, rowb, cwb, g, tg);
  CP_WAIT(1);
  __syncthreads();
  mainloop_h(smem, OFF_B1, f, rowb, cwb, lane);
  store_plain(f, p.acc, row0, p.M, rowb, cwb, g, tg);
  signal_cnt(2);                                       // ACC1 ready (syncs B1 reads)
  copy_B_async(smem, OFF_B1, p.wp + 2 * SLAB_B);       // Wc1b(L1) g3
  CP_WAIT(1);
  __syncthreads();
  mainloop_h(smem, OFF_B0, f, rowb, cwb, lane);
  gn_ep(f, smem, p.gnq_w, p.gnq_b, rowb, cwb, nw, g, tg, true);
  repack_A(f, smem, rowb, cwb, g, tg);
  CP_WAIT(0);
  __syncthreads();
  mainloop_h(smem, OFF_B1, f, rowb, cwb, lane);
  store_plain(f, p.qc, row0, p.M, rowb, cwb, g, tg);
  signal_cnt(3);                                       // P1 +1
}

// edge-job: dist-MLP -> ctx-MLP(+gathers after wait) -> scatter(after wait)
__device__ void job_edge(const P& p, int bid, char* smem,
                         int rowb, int cwb, int nw, int g, int tg, int lane) {
  const int row0 = bid * TMR;
  float f[2][8][4];
  copy_B_async(smem, OFF_B0, p.wp + 7 * SLAB_B);     // Wd2   g0
  copy_B_async(smem, OFF_B1, p.wp + 1 * SLAB_B);     // Wc1a  g1
  {
    const int q = threadIdx.x & 3;
    for (int r = threadIdx.x >> 2; r < TMR; r += 64) {
      const int gr = row0 + r;
      float cx = 0.f, cy = 0.f;
      if (gr < p.E) {
        int h = p.hi[gr], w = p.wi[gr];
        cx = p.actor_ctrs[2 * h]     - p.node_ctrs[2 * w];
        cy = p.actor_ctrs[2 * h + 1] - p.node_ctrs[2 * w + 1];
        PREF_L2(p.qc + (size_t)h * DCH + q * 32);
        PREF_L2(p.nc + (size_t)w * DCH + q * 32);
      }
      float v[32];
#pragma unroll
      for (int i = 0; i < 32; i++) {
        const int k = q * 32 + i;
        v[i] = fmaxf(fmaf(cx, p.Wd1[2 * k], fmaf(cy, p.Wd1[2 * k + 1], p.bd1[k])), 0.f);
      }
      store_A_h(smem, v, r, q);
    }
  }
  CP_WAIT(1);
  __syncthreads();
  mainloop_h(smem, OFF_B0, f, rowb, cwb, lane);
  gn_ep(f, smem, p.gnd2_w, p.gnd2_b, rowb, cwb, nw, g, tg, true);
  copy_B_async(smem, OFF_B0, p.wp + 4 * SLAB_B);     // Wc2  g2
  repack_A(f, smem, rowb, cwb, g, tg);
  CP_WAIT(1);
  __syncthreads();

  mainloop_h(smem, OFF_B1, f, rowb, cwb, lane);
  wait_cnt(p.cP, p.tP);                              // qc+nc ready
  {
    const int c0 = cwb + tg * 2;
#pragma unroll
    for (int ms = 0; ms < 2; ms++)
#pragma unroll
      for (int h = 0; h < 2; h++) {
        const int gr = row0 + rowb + ms * 16 + h * 8 + g;
        if (gr < p.E) {
          const float* p1 = p.qc + (size_t)p.hi[gr] * DCH + c0;
          const float* p2 = p.nc + (size_t)p.wi[gr] * DCH + c0;
#pragma unroll
          for (int ns = 0; ns < 8; ns++) {
            float2 v1 = *(const float2*)(p1 + ns * 8);
            float2 v2 = *(const float2*)(p2 + ns * 8);
            f[ms][ns][2 * h]     += v1.x + v2.x;
            f[ms][ns][2 * h + 1] += v1.y + v2.y;
          }
        }
      }
  }
  gn_ep(f, smem, p.gnc1_w, p.gnc1_b, rowb, cwb, nw, g, tg, true);
  repack_A(f, smem, rowb, cwb, g, tg);
  CP_WAIT(0);
  __syncthreads();

  mainloop_h(smem, OFF_B0, f, rowb, cwb, lane);
  wait_cnt(p.cA, p.mb);                              // acc base ready
  {
    const int c0 = cwb + tg * 2;
#pragma unroll
    for (int ms = 0; ms < 2; ms++)
#pragma unroll
      for (int h = 0; h < 2; h++) {
        const int gr = row0 + rowb + ms * 16 + h * 8 + g;
        if (gr < p.E) {
          float* dst = p.acc + (size_t)p.hi[gr] * DCH + c0;
#pragma unroll
          for (int ns = 0; ns < 8; ns++)
            REDV2(dst + ns * 8, f[ms][ns][2 * h], f[ms][ns][2 * h + 1]);
        }
      }
  }
  if (p.sigE) signal_cnt(4);                         // EDGE +1
}

// f-job: wait all scatters -> relu(gn(acc)) -> Wl -> gn + residual + relu -> out
__device__ void job_f(const P& p, int bid, char* smem,
                      int rowb, int cwb, int nw, int g, int tg, int lane) {
  const int row0 = bid * TMR;
  float f[2][8][4];
  copy_B_async(smem, OFF_B0, p.wp + 6 * SLAB_B);     // Wl (issued before wait)
  wait_cnt(4, p.eb);
  load_A_gn(smem, p.acc, row0, p.M, p.gnn_w, p.gnn_b);
  CP_WAIT(0);
  __syncthreads();
  mainloop_h(smem, OFF_B0, f, rowb, cwb, lane);
  gn_ep(f, smem, p.gnl_w, p.gnl_b, rowb, cwb, nw, g, tg, false);
  {
    const int c0 = cwb + tg * 2;
#pragma unroll
    for (int ms = 0; ms < 2; ms++)
#pragma unroll
      for (int h = 0; h < 2; h++) {
        const int gr = row0 + rowb + ms * 16 + h * 8 + g;
        if (gr < p.M) {
          const float* rp = p.agts + (size_t)gr * DCH + c0;
          float* dst = p.out + (size_t)gr * DCH + c0;
#pragma unroll
          for (int ns = 0; ns < 8; ns++) {
            float2 rv = *(const float2*)(rp + ns * 8);
            *(float2*)(dst + ns * 8) =
                make_float2(fmaxf(f[ms][ns][2 * h]     + rv.x, 0.f),
                            fmaxf(f[ms][ns][2 * h + 1] + rv.y, 0.f));
          }
        }
      }
  }
}

// ---------------- merged launches ----------------
__global__ void __launch_bounds__(256, 2) merge0_kernel(P p) {
  extern __shared__ char smem[];
  const int tid = threadIdx.x, warp = tid >> 5, lane = tid & 31;
  const int mw = warp & 3, nw = warp >> 2;
  const int rowb = mw * 32, cwb = nw * 64, g = lane >> 2, tg = lane & 3;
  const int b = blockIdx.x;
  if (b < p.mb)                job_agts0(p, b, smem, rowb, cwb, nw, g, tg, lane);
  else if (b < p.mb + p.nb)    job_nodes(p, b - p.mb, smem, rowb, cwb, nw, g, tg, lane);
  else                         job_edge(p, b - p.mb - p.nb, smem, rowb, cwb, nw, g, tg, lane);
}

__global__ void __launch_bounds__(256, 2) merge1_kernel(P p) {
  extern __shared__ char smem[];
  const int tid = threadIdx.x, warp = tid >> 5, lane = tid & 31;
  const int mw = warp & 3, nw = warp >> 2;
  const int rowb = mw * 32, cwb = nw * 64, g = lane >> 2, tg = lane & 3;
  const int b = blockIdx.x;
  if (b < p.mb)                job_mn1(p, b, smem, rowb, cwb, nw, g, tg, lane);
  else if (b < p.mb + p.eb)    job_edge(p, b - p.mb, smem, rowb, cwb, nw, g, tg, lane);
  else                         job_f(p, b - p.mb - p.eb, smem, rowb, cwb, nw, g, tg, lane);
}

extern "C" void kernel_launch(void* const* d_in, const int* in_sizes, int n_in,
                              void* d_out, int out_size) {
  const float* actors     = (const float*)d_in[0];
  const float* nodes      = (const float*)d_in[1];
  const float* actor_ctrs = (const float*)d_in[2];
  const float* node_ctrs  = (const float*)d_in[3];
  const int*   hi         = (const int*)d_in[4];
  const int*   wi         = (const int*)d_in[5];
  const float* Wd1   = (const float*)d_in[6];
  const float* bd1   = (const float*)d_in[7];
  const float* Wd2   = (const float*)d_in[8];
  const float* gnd2w = (const float*)d_in[9];
  const float* gnd2b = (const float*)d_in[10];
  const float* Wq    = (const float*)d_in[11];
  const float* gnqw  = (const float*)d_in[12];
  const float* gnqb  = (const float*)d_in[13];
  const float* Wc1   = (const float*)d_in[14];
  const float* gnc1w = (const float*)d_in[15];
  const float* gnc1b = (const float*)d_in[16];
  const float* Wc2   = (const float*)d_in[17];
  const float* Wa    = (const float*)d_in[18];
  const float* gnnw  = (const float*)d_in[19];
  const float* gnnb  = (const float*)d_in[20];
  const float* Wl    = (const float*)d_in[21];
  const float* gnlw  = (const float*)d_in[22];
  const float* gnlb  = (const float*)d_in[23];

  const int M = in_sizes[0] / DCH;
  const int N = in_sizes[1] / DCH;
  const int E = in_sizes[4];

  float *qc, *nc0, *nc1, *accb, *agts1;
  unsigned char* wp;
  cudaGetSymbolAddress((void**)&qc,    g_qc);
  cudaGetSymbolAddress((void**)&nc0,   g_nc0);
  cudaGetSymbolAddress((void**)&nc1,   g_nc1);
  cudaGetSymbolAddress((void**)&accb,  g_acc);
  cudaGetSymbolAddress((void**)&agts1, g_agts);
  cudaGetSymbolAddress((void**)&wp,    g_wp);

  cudaFuncSetAttribute(merge0_kernel, cudaFuncAttributeMaxDynamicSharedMemorySize, SMEM_SZ);
  cudaFuncSetAttribute(merge1_kernel, cudaFuncAttributeMaxDynamicSharedMemorySize, SMEM_SZ);

  const int mb = (M + TMR - 1) / TMR;
  const int nb = (N + TMR - 1) / TMR;
  const int eb = (E + TMR - 1) / TMR;

  wpack_kernel<<<16, 128>>>(Wq, Wc1, Wc2, Wa, Wl, Wd2, wp);

  P base = {};
  base.nodes = nodes;
  base.actor_ctrs = actor_ctrs;
  base.node_ctrs = node_ctrs;
  base.hi = hi; base.wi = wi;
  base.qc = qc; base.acc = accb; base.agts1 = agts1;
  base.M = M; base.N = N; base.E = E; base.mb = mb; base.nb = nb; base.eb = eb;

  const unsigned char* wp0 = wp;
  const unsigned char* wp1 = wp + (size_t)8 * SLAB_B;

  // ---- merged layer 0: agts-job + nodes-job + edges ----
  {
    P p = base;
    p.agts = actors;
    p.wp = wp0; p.wpPrev = wp1;
    p.Wd1 = Wd1; p.bd1 = bd1;
    p.gnq_w = gnqw;  p.gnq_b = gnqb;
    p.gnd2_w = gnd2w; p.gnd2_b = gnd2b;
    p.gnc1_w = gnc1w; p.gnc1_b = gnc1b;
    p.nc = nc0; p.nc1 = nc1;
    p.cP = 1; p.tP = mb + nb; p.cA = 0; p.sigE = 0;
    merge0_kernel<<<mb + nb + eb, 256, SMEM_SZ>>>(p);
  }
  // ---- merged layer 1: mn1 + edges + f ----
  {
    P p = base;
    p.wp = wp1; p.wpPrev = wp0;
    p.res = actors;
    p.gnn0_w = gnnw; p.gnn0_b = gnnb;            // L0 gn_n (recompute)
    p.gnl0_w = gnlw; p.gnl0_b = gnlb;            // L0 gn_l (recompute)
    p.gnq_w = gnqw + DCH; p.gnq_b = gnqb + DCH;
    p.Wd1 = Wd1 + DCH * 2; p.bd1 = bd1 + DCH;
    p.gnd2_w = gnd2w + DCH; p.gnd2_b = gnd2b + DCH;
    p.gnc1_w = gnc1w + DCH; p.gnc1_b = gnc1b + DCH;
    p.gnn_w = gnnw + DCH; p.gnn_b = gnnb + DCH;  // L1 f
    p.gnl_w = gnlw + DCH; p.gnl_b = gnlb + DCH;
    p.nc = nc1;
    p.agts = agts1;                              // residual for f
    p.out = (float*)d_out;
    p.cP = 3; p.tP = mb; p.cA = 2; p.sigE = 1;
    merge1_kernel<<<mb + eb + mb, 256, SMEM_SZ>>>(p);
  }
}

// round 16
// speedup vs baseline: 1.0330x; 1.0330x over previous
#include <cuda_runtime.h>
#include <cuda_fp16.h>
#include <cstdint>

#define DCH 128
#define TMR 128
#define ROWB 272               // 256B data + 16B pad

#define OFF_A   0
#define OFF_B0  (128 * ROWB)
#define OFF_B1  (2 * 128 * ROWB)
#define OFF_PS  (3 * 128 * ROWB)
#define SMEM_SZ (OFF_PS + 2048 + 64)

#define SLAB_B  (128 * 256)

// counters: 4=EDGE0 5=EDGE1
__device__ int g_cnt[8];

// ---------------- scratch (alloc-free) ----------------
__device__ float g_qc[4000 * 128];
__device__ float g_nc0[20000 * 128];
__device__ float g_nc1[20000 * 128];
__device__ float g_acc[4000 * 128];
__device__ float g_agts[4000 * 128];
__device__ __align__(16) unsigned char g_wp[2 * 8 * SLAB_B];

// slabs: 0=Wq 1=Wc1a 2=Wc1b 3=Wc1c 4=Wc2 5=Wa 6=Wl 7=Wd2

struct P {
  const float* agts; const float* nodes;
  const float* actor_ctrs; const float* node_ctrs;
  const int* hi; const int* wi;
  const unsigned char* wp;      // this layer's slabs (edge / mn0 / f jobs)
  const unsigned char* wpNext;  // next layer's slabs (nodes-job nc1, mn1 L1 weights)
  const float* Wd1; const float* bd1;
  const float *gnq_w, *gnq_b, *gnd2_w, *gnd2_b, *gnc1_w, *gnc1_b,
              *gnn_w, *gnn_b, *gnl_w, *gnl_b;
  const float* res;
  float *qc, *nc, *nc1, *acc, *agts1, *out;
  int M, N, E, mb, nb, eb;
  int sigE;                     // edge-completion counter idx
};

__device__ __forceinline__ uint32_t smem_u32(const void* p) {
  uint32_t a;
  asm("{ .reg .u64 t; cvta.to.shared.u64 t, %1; cvt.u32.u64 %0, t; }" : "=r"(a) : "l"(p));
  return a;
}
#define LDSM4(r0, r1, r2, r3, addr) \
  asm volatile("ldmatrix.sync.aligned.m8n8.x4.shared.b16 {%0,%1,%2,%3}, [%4];" \
    : "=r"(r0), "=r"(r1), "=r"(r2), "=r"(r3) : "r"(addr))
#define STS32(addr, v) \
  asm volatile("st.shared.u32 [%0], %1;" :: "r"(addr), "r"(v))
#define CP_A16(dst, src) \
  asm volatile("cp.async.cg.shared.global [%0], [%1], 16;" :: "r"(dst), "l"(src))
#define CP_COMMIT() asm volatile("cp.async.commit_group;" ::: "memory")
#define CP_WAIT(n)  asm volatile("cp.async.wait_group %0;" :: "n"(n) : "memory")
#define REDV2(ptr, x, y) \
  asm volatile("red.global.v2.f32.add [%0], {%1, %2};" :: "l"(ptr), "f"(x), "f"(y) : "memory")
#define PREF_L2(ptr) asm volatile("prefetch.global.L2 [%0];" :: "l"(ptr))

__device__ __forceinline__ void signal_cnt(int idx) {
  __syncthreads();
  __threadfence();
  if (threadIdx.x == 0) atomicAdd(&g_cnt[idx], 1);
}
__device__ __forceinline__ void wait_cnt(int idx, int target) {
  if (threadIdx.x == 0) {
    while (atomicAdd(&g_cnt[idx], 0) < target) __nanosleep(256);
    __threadfence();
  }
  __syncthreads();
}

__device__ __forceinline__ uint32_t h2pack(float lo, float hi) {
  uint32_t r;
  asm("cvt.rn.f16x2.f32 %0, %1, %2;" : "=r"(r) : "f"(hi), "f"(lo));
  return r;
}

__device__ __forceinline__ void mma_h(float c[4], const uint32_t a[4],
                                      uint32_t b0, uint32_t b1) {
  asm volatile(
    "mma.sync.aligned.m16n8k16.row.col.f32.f16.f16.f32 "
    "{%0,%1,%2,%3}, {%4,%5,%6,%7}, {%8,%9}, {%0,%1,%2,%3};"
    : "+f"(c[0]), "+f"(c[1]), "+f"(c[2]), "+f"(c[3])
    : "r"(a[0]), "r"(a[1]), "r"(a[2]), "r"(a[3]), "r"(b0), "r"(b1));
}

__device__ __forceinline__ void store_A_h(char* smem, const float v[32], int r, int q) {
  char* rowp = smem + OFF_A + r * ROWB + q * 64;
#pragma unroll
  for (int a = 0; a < 4; a++) {
    uint4 o = make_uint4(h2pack(v[8 * a],     v[8 * a + 1]),
                         h2pack(v[8 * a + 2], v[8 * a + 3]),
                         h2pack(v[8 * a + 4], v[8 * a + 5]),
                         h2pack(v[8 * a + 6], v[8 * a + 7]));
    *(uint4*)(rowp + a * 16) = o;
  }
}

__device__ __forceinline__ void copy_B_async(char* smem, int bOff, const unsigned char* wps) {
  const uint32_t dst = smem_u32(smem) + bOff;
  for (int i = threadIdx.x; i < 2048; i += 256) {
    int row = i >> 4, u = i & 15;
    CP_A16(dst + row * ROWB + u * 16, wps + (size_t)i * 16);
  }
  CP_COMMIT();
}

__device__ __forceinline__ void mainloop_h(const char* smem, int bOff, float acc[2][8][4],
                                           int rowb, int cwb, int lane) {
  const uint32_t Ab = smem_u32(smem) + OFF_A;
  const uint32_t Bb = smem_u32(smem) + bOff;
  const uint32_t aAddr = Ab + (rowb + (lane & 15)) * ROWB + ((lane >> 4) << 4);
  const uint32_t bAddr = Bb + (cwb + ((lane >> 4) << 3) + (lane & 7)) * ROWB
                            + ((lane & 8) ? 16 : 0);
#pragma unroll
  for (int ms = 0; ms < 2; ms++)
#pragma unroll
    for (int ns = 0; ns < 8; ns++)
#pragma unroll
      for (int q = 0; q < 4; q++) acc[ms][ns][q] = 0.f;
#pragma unroll
  for (int ks = 0; ks < 8; ks++) {
    uint32_t a[2][4], b[4][4];
    LDSM4(a[0][0], a[0][1], a[0][2], a[0][3], aAddr + ks * 32);
    LDSM4(a[1][0], a[1][1], a[1][2], a[1][3], aAddr + 16 * ROWB + ks * 32);
#pragma unroll
    for (int pr = 0; pr < 4; pr++)
      LDSM4(b[pr][0], b[pr][1], b[pr][2], b[pr][3], bAddr + pr * 16 * ROWB + ks * 32);
#pragma unroll
    for (int ns = 0; ns < 8; ns++) {
      uint32_t b0 = b[ns >> 1][(ns & 1) * 2], b1 = b[ns >> 1][(ns & 1) * 2 + 1];
      mma_h(acc[0][ns], a[0], b0, b1);
      mma_h(acc[1][ns], a[1], b0, b1);
    }
  }
}

__device__ __forceinline__ void gn_ep(float f[2][8][4], char* smem,
                                      const float* gnw, const float* gnb,
                                      int rowb, int cwb, int nw, int g, int tg,
                                      bool dorelu) {
  float* ps = (float*)(smem + OFF_PS);
  float* pq = ps + 256;
#pragma unroll
  for (int ms = 0; ms < 2; ms++)
#pragma unroll
    for (int h = 0; h < 2; h++) {
      float s = 0.f, q = 0.f;
#pragma unroll
      for (int ns = 0; ns < 8; ns++)
#pragma unroll
        for (int j = 0; j < 2; j++) {
          float v = f[ms][ns][2 * h + j];
          s += v;
          q = fmaf(v, v, q);
        }
      s += __shfl_xor_sync(0xffffffffu, s, 1);
      q += __shfl_xor_sync(0xffffffffu, q, 1);
      s += __shfl_xor_sync(0xffffffffu, s, 2);
      q += __shfl_xor_sync(0xffffffffu, q, 2);
      const int r = rowb + ms * 16 + h * 8 + g;
      if (tg == 0) { ps[nw * 128 + r] = s; pq[nw * 128 + r] = q; }
    }
  __syncthreads();
  const int c0 = cwb + tg * 2;
#pragma unroll
  for (int ms = 0; ms < 2; ms++)
#pragma unroll
    for (int h = 0; h < 2; h++) {
      const int r = rowb + ms * 16 + h * 8 + g;
      float s = ps[r] + ps[128 + r];
      float q = pq[r] + pq[128 + r];
      float m = s * (1.f / DCH);
      float var = q * (1.f / DCH) - m * m;
      float inv = rsqrtf(var + 1e-5f);
#pragma unroll
      for (int ns = 0; ns < 8; ns++) {
        float2 gw = *(const float2*)(gnw + c0 + ns * 8);
        float2 gb = *(const float2*)(gnb + c0 + ns * 8);
        float a0 = fmaf((f[ms][ns][2 * h]     - m) * inv, gw.x, gb.x);
        float a1 = fmaf((f[ms][ns][2 * h + 1] - m) * inv, gw.y, gb.y);
        if (dorelu) { a0 = fmaxf(a0, 0.f); a1 = fmaxf(a1, 0.f); }
        f[ms][ns][2 * h]     = a0;
        f[ms][ns][2 * h + 1] = a1;
      }
    }
}

__device__ __forceinline__ void repack_A(const float f[2][8][4], char* smem,
                                         int rowb, int cwb, int g, int tg) {
  const uint32_t Ab = smem_u32(smem) + OFF_A;
#pragma unroll
  for (int ms = 0; ms < 2; ms++)
#pragma unroll
    for (int h = 0; h < 2; h++) {
      const int r = rowb + ms * 16 + h * 8 + g;
#pragma unroll
      for (int ns = 0; ns < 8; ns++) {
        const int c = cwb + ns * 8 + tg * 2;
        STS32(Ab + r * ROWB + c * 2, h2pack(f[ms][ns][2 * h], f[ms][ns][2 * h + 1]));
      }
    }
}

__device__ __forceinline__ void store_plain(const float f[2][8][4], float* Y, int row0,
                                            int rows, int rowb, int cwb, int g, int tg) {
  const int c0 = cwb + tg * 2;
#pragma unroll
  for (int ms = 0; ms < 2; ms++)
#pragma unroll
    for (int h = 0; h < 2; h++) {
      const int gr = row0 + rowb + ms * 16 + h * 8 + g;
      if (gr < rows) {
        float* dst = Y + (size_t)gr * DCH + c0;
#pragma unroll
        for (int ns = 0; ns < 8; ns++)
          *(float2*)(dst + ns * 8) =
              make_float2(f[ms][ns][2 * h], f[ms][ns][2 * h + 1]);
      }
    }
}

__device__ __forceinline__ void load_A_h(char* smem, const float* X, int row0, int rows) {
  const int q = threadIdx.x & 3;
  for (int r = threadIdx.x >> 2; r < TMR; r += 64) {
    const int gr = row0 + r;
    const float* px = X + (size_t)gr * DCH + q * 32;
    float v[32];
#pragma unroll
    for (int i = 0; i < 8; i++) {
      float4 t = (gr < rows) ? *(const float4*)(px + 4 * i) : make_float4(0.f, 0.f, 0.f, 0.f);
      v[4 * i] = t.x; v[4 * i + 1] = t.y; v[4 * i + 2] = t.z; v[4 * i + 3] = t.w;
    }
    store_A_h(smem, v, r, q);
  }
}

// load A = relu(gn(X)) rows — L2-coherent reads (X mutated by red.global in-launch)
__device__ __forceinline__ void load_A_gn(char* smem, const float* X, int row0, int rows,
                                          const float* gnw, const float* gnb) {
  const int q = threadIdx.x & 3;
  for (int r = threadIdx.x >> 2; r < TMR; r += 64) {
    const int gr = row0 + r;
    float v[32];
    const float4* px = (const float4*)(X + (size_t)gr * DCH + q * 32);
#pragma unroll
    for (int i = 0; i < 8; i++) {
      float4 t = (gr < rows) ? __ldcg(px + i) : make_float4(0.f, 0.f, 0.f, 0.f);
      v[4 * i] = t.x; v[4 * i + 1] = t.y; v[4 * i + 2] = t.z; v[4 * i + 3] = t.w;
    }
    float s = 0.f, qq = 0.f;
#pragma unroll
    for (int i = 0; i < 32; i++) { s += v[i]; qq = fmaf(v[i], v[i], qq); }
    s  += __shfl_xor_sync(0xffffffffu, s, 1);
    qq += __shfl_xor_sync(0xffffffffu, qq, 1);
    s  += __shfl_xor_sync(0xffffffffu, s, 2);
    qq += __shfl_xor_sync(0xffffffffu, qq, 2);
    float m = s * (1.f / DCH);
    float var = qq * (1.f / DCH) - m * m;
    float inv = rsqrtf(var + 1e-5f);
#pragma unroll
    for (int i = 0; i < 32; i++) {
      const int c = q * 32 + i;
      v[i] = fmaxf(fmaf((v[i] - m) * inv, gnw[c], gnb[c]), 0.f);
    }
    store_A_h(smem, v, r, q);
  }
}

// ---------------- wide weight pack (grid 32 x 256) ----------------
__global__ void wpack_kernel(const float* Wq, const float* Wc1, const float* Wc2,
                             const float* Wa, const float* Wl, const float* Wd2,
                             unsigned char* wp) {
  if (blockIdx.x == 0 && threadIdx.x < 8) g_cnt[threadIdx.x] = 0;
  const int sid = blockIdx.x >> 1;       // slab 0..15
  const int L = sid >> 3, s = sid & 7;
  const float* src;
  int ldw = DCH, coff = 0;
  switch (s) {
    case 0: src = Wq  + (size_t)L * DCH * DCH; break;
    case 1: src = Wc1 + (size_t)L * DCH * 3 * DCH; ldw = 3 * DCH; coff = 0;       break;
    case 2: src = Wc1 + (size_t)L * DCH * 3 * DCH; ldw = 3 * DCH; coff = DCH;     break;
    case 3: src = Wc1 + (size_t)L * DCH * 3 * DCH; ldw = 3 * DCH; coff = 2 * DCH; break;
    case 4: src = Wc2 + (size_t)L * DCH * DCH; break;
    case 5: src = Wa  + (size_t)L * DCH * DCH; break;
    case 6: src = Wl  + (size_t)L * DCH * DCH; break;
    default: src = Wd2 + (size_t)L * DCH * DCH; break;
  }
  unsigned char* dst = wp + (size_t)sid * SLAB_B;
  const int j = (blockIdx.x & 1) * 64 + (threadIdx.x >> 2);   // row 0..127
  const int q = threadIdx.x & 3;                              // col quarter
  const float4* wr4 = (const float4*)(src + (size_t)j * ldw + coff + q * 32);
  unsigned char* drow = dst + (size_t)j * 256 + q * 64;
#pragma unroll
  for (int a = 0; a < 4; a++) {
    float4 v0 = wr4[2 * a], v1 = wr4[2 * a + 1];
    uint4 o = make_uint4(h2pack(v0.x, v0.y), h2pack(v0.z, v0.w),
                         h2pack(v1.x, v1.y), h2pack(v1.z, v1.w));
    *(uint4*)(drow + a * 16) = o;
  }
}

// ---------------- jobs ----------------
// agts-job (layer0): Wa->acc, Wq->gn->repack, Wc1b->qc
__device__ void job_agts0(const P& p, int bid, char* smem,
                          int rowb, int cwb, int nw, int g, int tg, int lane) {
  const int row0 = bid * TMR;
  float f[2][8][4];
  copy_B_async(smem, OFF_B0, p.wp + 5 * SLAB_B);   // Wa   g0
  copy_B_async(smem, OFF_B1, p.wp + 0 * SLAB_B);   // Wq   g1
  load_A_h(smem, p.agts, row0, p.M);
  CP_WAIT(1);
  __syncthreads();
  mainloop_h(smem, OFF_B0, f, rowb, cwb, lane);
  store_plain(f, p.acc, row0, p.M, rowb, cwb, g, tg);
  __syncthreads();                                 // B0 reads done
  copy_B_async(smem, OFF_B0, p.wp + 2 * SLAB_B);   // Wc1b g2
  CP_WAIT(1);
  __syncthreads();
  mainloop_h(smem, OFF_B1, f, rowb, cwb, lane);
  gn_ep(f, smem, p.gnq_w, p.gnq_b, rowb, cwb, nw, g, tg, true);
  repack_A(f, smem, rowb, cwb, g, tg);
  CP_WAIT(0);
  __syncthreads();
  mainloop_h(smem, OFF_B0, f, rowb, cwb, lane);
  store_plain(f, p.qc, row0, p.M, rowb, cwb, g, tg);
}

// nodes-job: nc0, nc1 (both layers off one A load)
__device__ void job_nodes(const P& p, int bid, char* smem,
                          int rowb, int cwb, int nw, int g, int tg, int lane) {
  const int row0 = bid * TMR;
  float f[2][8][4];
  copy_B_async(smem, OFF_B0, p.wp + 3 * SLAB_B);       // Wc1c L0
  copy_B_async(smem, OFF_B1, p.wpNext + 3 * SLAB_B);   // Wc1c L1
  load_A_h(smem, p.nodes, row0, p.N);
  CP_WAIT(1);
  __syncthreads();
  mainloop_h(smem, OFF_B0, f, rowb, cwb, lane);
  store_plain(f, p.nc, row0, p.N, rowb, cwb, g, tg);
  CP_WAIT(0);
  __syncthreads();
  mainloop_h(smem, OFF_B1, f, rowb, cwb, lane);
  store_plain(f, p.nc1, row0, p.N, rowb, cwb, g, tg);
}

// edge-job: dist-MLP -> ctx-MLP(+gathers) -> scatter; NO waits, signals sigE
__device__ void job_edge(const P& p, int bid, char* smem,
                         int rowb, int cwb, int nw, int g, int tg, int lane) {
  const int row0 = bid * TMR;
  float f[2][8][4];
  copy_B_async(smem, OFF_B0, p.wp + 7 * SLAB_B);     // Wd2   g0
  copy_B_async(smem, OFF_B1, p.wp + 1 * SLAB_B);     // Wc1a  g1
  {
    const int q = threadIdx.x & 3;
    for (int r = threadIdx.x >> 2; r < TMR; r += 64) {
      const int gr = row0 + r;
      float cx = 0.f, cy = 0.f;
      if (gr < p.E) {
        int h = p.hi[gr], w = p.wi[gr];
        cx = p.actor_ctrs[2 * h]     - p.node_ctrs[2 * w];
        cy = p.actor_ctrs[2 * h + 1] - p.node_ctrs[2 * w + 1];
        PREF_L2(p.qc + (size_t)h * DCH + q * 32);
        PREF_L2(p.nc + (size_t)w * DCH + q * 32);
      }
      float v[32];
#pragma unroll
      for (int i = 0; i < 32; i++) {
        const int k = q * 32 + i;
        v[i] = fmaxf(fmaf(cx, p.Wd1[2 * k], fmaf(cy, p.Wd1[2 * k + 1], p.bd1[k])), 0.f);
      }
      store_A_h(smem, v, r, q);
    }
  }
  CP_WAIT(1);
  __syncthreads();
  mainloop_h(smem, OFF_B0, f, rowb, cwb, lane);
  gn_ep(f, smem, p.gnd2_w, p.gnd2_b, rowb, cwb, nw, g, tg, true);
  copy_B_async(smem, OFF_B0, p.wp + 4 * SLAB_B);     // Wc2  g2
  repack_A(f, smem, rowb, cwb, g, tg);
  CP_WAIT(1);
  __syncthreads();

  mainloop_h(smem, OFF_B1, f, rowb, cwb, lane);
  {
    const int c0 = cwb + tg * 2;
#pragma unroll
    for (int ms = 0; ms < 2; ms++)
#pragma unroll
      for (int h = 0; h < 2; h++) {
        const int gr = row0 + rowb + ms * 16 + h * 8 + g;
        if (gr < p.E) {
          const float* p1 = p.qc + (size_t)p.hi[gr] * DCH + c0;
          const float* p2 = p.nc + (size_t)p.wi[gr] * DCH + c0;
#pragma unroll
          for (int ns = 0; ns < 8; ns++) {
            float2 v1 = *(const float2*)(p1 + ns * 8);
            float2 v2 = *(const float2*)(p2 + ns * 8);
            f[ms][ns][2 * h]     += v1.x + v2.x;
            f[ms][ns][2 * h + 1] += v1.y + v2.y;
          }
        }
      }
  }
  gn_ep(f, smem, p.gnc1_w, p.gnc1_b, rowb, cwb, nw, g, tg, true);
  repack_A(f, smem, rowb, cwb, g, tg);
  CP_WAIT(0);
  __syncthreads();

  mainloop_h(smem, OFF_B0, f, rowb, cwb, lane);
  {
    const int c0 = cwb + tg * 2;
#pragma unroll
    for (int ms = 0; ms < 2; ms++)
#pragma unroll
      for (int h = 0; h < 2; h++) {
        const int gr = row0 + rowb + ms * 16 + h * 8 + g;
        if (gr < p.E) {
          float* dst = p.acc + (size_t)p.hi[gr] * DCH + c0;
#pragma unroll
          for (int ns = 0; ns < 8; ns++)
            REDV2(dst + ns * 8, f[ms][ns][2 * h], f[ms][ns][2 * h + 1]);
        }
      }
  }
  signal_cnt(p.sigE);
}

// mn1 tail-job (in e0 launch): waits EDGE0, then f-recompute(L0)->agts1,
// Wa(L1)->acc, Wq(L1), Wc1b(L1)->qc
__device__ void job_mn1(const P& p, int bid, char* smem,
                        int rowb, int cwb, int nw, int g, int tg, int lane) {
  const int row0 = bid * TMR;
  float f[2][8][4];
  copy_B_async(smem, OFF_B0, p.wp + 6 * SLAB_B);       // Wl(L0)  g0  (pre-wait)
  copy_B_async(smem, OFF_B1, p.wpNext + 5 * SLAB_B);   // Wa(L1)  g1  (pre-wait)
  wait_cnt(p.sigE, p.eb);                              // all e0 scatters + reads done
  load_A_gn(smem, p.acc, row0, p.M, p.gnn_w, p.gnn_b); // gnn = L0 gn_n
  CP_WAIT(1);
  __syncthreads();
  mainloop_h(smem, OFF_B0, f, rowb, cwb, lane);
  gn_ep(f, smem, p.gnl_w, p.gnl_b, rowb, cwb, nw, g, tg, false);   // gnl = L0 gn_l
  {
    const int c0 = cwb + tg * 2;
#pragma unroll
    for (int ms = 0; ms < 2; ms++)
#pragma unroll
      for (int h = 0; h < 2; h++) {
        const int gr = row0 + rowb + ms * 16 + h * 8 + g;
        if (gr < p.M) {
          const float* rp = p.res + (size_t)gr * DCH + c0;
#pragma unroll
          for (int ns = 0; ns < 8; ns++) {
            float2 rv = *(const float2*)(rp + ns * 8);
            f[ms][ns][2 * h]     = fmaxf(f[ms][ns][2 * h]     + rv.x, 0.f);
            f[ms][ns][2 * h + 1] = fmaxf(f[ms][ns][2 * h + 1] + rv.y, 0.f);
          }
        } else {
#pragma unroll
          for (int ns = 0; ns < 8; ns++) {
            f[ms][ns][2 * h] = 0.f;
            f[ms][ns][2 * h + 1] = 0.f;
          }
        }
      }
  }
  store_plain(f, p.agts1, row0, p.M, rowb, cwb, g, tg);
  copy_B_async(smem, OFF_B0, p.wpNext + 0 * SLAB_B);   // Wq(L1)  g2
  repack_A(f, smem, rowb, cwb, g, tg);
  CP_WAIT(1);
  __syncthreads();
  mainloop_h(smem, OFF_B1, f, rowb, cwb, lane);        // Wa
  store_plain(f, p.acc, row0, p.M, rowb, cwb, g, tg);
  __syncthreads();                                     // B1 reads done
  copy_B_async(smem, OFF_B1, p.wpNext + 2 * SLAB_B);   // Wc1b(L1) g3
  CP_WAIT(1);
  __syncthreads();
  mainloop_h(smem, OFF_B0, f, rowb, cwb, lane);        // Wq
  gn_ep(f, smem, p.gnq_w, p.gnq_b, rowb, cwb, nw, g, tg, true);    // gnq = L1
  repack_A(f, smem, rowb, cwb, g, tg);
  CP_WAIT(0);
  __syncthreads();
  mainloop_h(smem, OFF_B1, f, rowb, cwb, lane);        // Wc1b
  store_plain(f, p.qc, row0, p.M, rowb, cwb, g, tg);
}

// f tail-job (in e1 launch): waits EDGE1 -> relu(gn(acc)) -> Wl -> gn + res -> out
__device__ void job_f(const P& p, int bid, char* smem,
                      int rowb, int cwb, int nw, int g, int tg, int lane) {
  const int row0 = bid * TMR;
  float f[2][8][4];
  copy_B_async(smem, OFF_B0, p.wp + 6 * SLAB_B);     // Wl (pre-wait)
  wait_cnt(p.sigE, p.eb);
  load_A_gn(smem, p.acc, row0, p.M, p.gnn_w, p.gnn_b);
  CP_WAIT(0);
  __syncthreads();
  mainloop_h(smem, OFF_B0, f, rowb, cwb, lane);
  gn_ep(f, smem, p.gnl_w, p.gnl_b, rowb, cwb, nw, g, tg, false);
  {
    const int c0 = cwb + tg * 2;
#pragma unroll
    for (int ms = 0; ms < 2; ms++)
#pragma unroll
      for (int h = 0; h < 2; h++) {
        const int gr = row0 + rowb + ms * 16 + h * 8 + g;
        if (gr < p.M) {
          const float* rp = p.agts + (size_t)gr * DCH + c0;
          float* dst = p.out + (size_t)gr * DCH + c0;
#pragma unroll
          for (int ns = 0; ns < 8; ns++) {
            float2 rv = *(const float2*)(rp + ns * 8);
            *(float2*)(dst + ns * 8) =
                make_float2(fmaxf(f[ms][ns][2 * h]     + rv.x, 0.f),
                            fmaxf(f[ms][ns][2 * h + 1] + rv.y, 0.f));
          }
        }
      }
  }
}

// ---------------- launches ----------------
__global__ void __launch_bounds__(256, 2) mn0_kernel(P p) {
  extern __shared__ char smem[];
  const int tid = threadIdx.x, warp = tid >> 5, lane = tid & 31;
  const int mw = warp & 3, nw = warp >> 2;
  const int rowb = mw * 32, cwb = nw * 64, g = lane >> 2, tg = lane & 3;
  const int b = blockIdx.x;
  if (b < p.mb) job_agts0(p, b, smem, rowb, cwb, nw, g, tg, lane);
  else          job_nodes(p, b - p.mb, smem, rowb, cwb, nw, g, tg, lane);
}

__global__ void __launch_bounds__(256, 2) eA_kernel(P p) {   // e0 edges + mn1 tail
  extern __shared__ char smem[];
  const int tid = threadIdx.x, warp = tid >> 5, lane = tid & 31;
  const int mw = warp & 3, nw = warp >> 2;
  const int rowb = mw * 32, cwb = nw * 64, g = lane >> 2, tg = lane & 3;
  const int b = blockIdx.x;
  if (b < p.eb) job_edge(p, b, smem, rowb, cwb, nw, g, tg, lane);
  else          job_mn1(p, b - p.eb, smem, rowb, cwb, nw, g, tg, lane);
}

__global__ void __launch_bounds__(256, 2) eB_kernel(P p) {   // e1 edges + f tail
  extern __shared__ char smem[];
  const int tid = threadIdx.x, warp = tid >> 5, lane = tid & 31;
  const int mw = warp & 3, nw = warp >> 2;
  const int rowb = mw * 32, cwb = nw * 64, g = lane >> 2, tg = lane & 3;
  const int b = blockIdx.x;
  if (b < p.eb) job_edge(p, b, smem, rowb, cwb, nw, g, tg, lane);
  else          job_f(p, b - p.eb, smem, rowb, cwb, nw, g, tg, lane);
}

extern "C" void kernel_launch(void* const* d_in, const int* in_sizes, int n_in,
                              void* d_out, int out_size) {
  const float* actors     = (const float*)d_in[0];
  const float* nodes      = (const float*)d_in[1];
  const float* actor_ctrs = (const float*)d_in[2];
  const float* node_ctrs  = (const float*)d_in[3];
  const int*   hi         = (const int*)d_in[4];
  const int*   wi         = (const int*)d_in[5];
  const float* Wd1   = (const float*)d_in[6];
  const float* bd1   = (const float*)d_in[7];
  const float* Wd2   = (const float*)d_in[8];
  const float* gnd2w = (const float*)d_in[9];
  const float* gnd2b = (const float*)d_in[10];
  const float* Wq    = (const float*)d_in[11];
  const float* gnqw  = (const float*)d_in[12];
  const float* gnqb  = (const float*)d_in[13];
  const float* Wc1   = (const float*)d_in[14];
  const float* gnc1w = (const float*)d_in[15];
  const float* gnc1b = (const float*)d_in[16];
  const float* Wc2   = (const float*)d_in[17];
  const float* Wa    = (const float*)d_in[18];
  const float* gnnw  = (const float*)d_in[19];
  const float* gnnb  = (const float*)d_in[20];
  const float* Wl    = (const float*)d_in[21];
  const float* gnlw  = (const float*)d_in[22];
  const float* gnlb  = (const float*)d_in[23];

  const int M = in_sizes[0] / DCH;
  const int N = in_sizes[1] / DCH;
  const int E = in_sizes[4];

  float *qc, *nc0, *nc1, *accb, *agts1;
  unsigned char* wp;
  cudaGetSymbolAddress((void**)&qc,    g_qc);
  cudaGetSymbolAddress((void**)&nc0,   g_nc0);
  cudaGetSymbolAddress((void**)&nc1,   g_nc1);
  cudaGetSymbolAddress((void**)&accb,  g_acc);
  cudaGetSymbolAddress((void**)&agts1, g_agts);
  cudaGetSymbolAddress((void**)&wp,    g_wp);

  cudaFuncSetAttribute(mn0_kernel, cudaFuncAttributeMaxDynamicSharedMemorySize, SMEM_SZ);
  cudaFuncSetAttribute(eA_kernel,  cudaFuncAttributeMaxDynamicSharedMemorySize, SMEM_SZ);
  cudaFuncSetAttribute(eB_kernel,  cudaFuncAttributeMaxDynamicSharedMemorySize, SMEM_SZ);

  const int mb = (M + TMR - 1) / TMR;
  const int nb = (N + TMR - 1) / TMR;
  const int eb = (E + TMR - 1) / TMR;

  wpack_kernel<<<32, 256>>>(Wq, Wc1, Wc2, Wa, Wl, Wd2, wp);

  P base = {};
  base.nodes = nodes;
  base.actor_ctrs = actor_ctrs;
  base.node_ctrs = node_ctrs;
  base.hi = hi; base.wi = wi;
  base.qc = qc; base.acc = accb; base.agts1 = agts1;
  base.M = M; base.N = N; base.E = E; base.mb = mb; base.nb = nb; base.eb = eb;

  const unsigned char* wp0 = wp;
  const unsigned char* wp1 = wp + (size_t)8 * SLAB_B;

  // ---- mn0: agts-job (L0) + nodes-job (both layers) ----
  {
    P p = base;
    p.agts = actors;
    p.wp = wp0; p.wpNext = wp1;
    p.gnq_w = gnqw; p.gnq_b = gnqb;
    p.nc = nc0; p.nc1 = nc1;
    mn0_kernel<<<mb + nb, 256, SMEM_SZ>>>(p);
  }
  // ---- e0 edges + mn1 tail ----
  {
    P p = base;
    p.wp = wp0; p.wpNext = wp1;
    p.Wd1 = Wd1; p.bd1 = bd1;
    p.gnd2_w = gnd2w; p.gnd2_b = gnd2b;
    p.gnc1_w = gnc1w; p.gnc1_b = gnc1b;
    p.nc = nc0;
    // mn1 params: L0 f-recompute + L1 producer
    p.res = actors;
    p.gnn_w = gnnw; p.gnn_b = gnnb;                  // L0 gn_n
    p.gnl_w = gnlw; p.gnl_b = gnlb;                  // L0 gn_l
    p.gnq_w = gnqw + DCH; p.gnq_b = gnqb + DCH;      // L1 gn_q
    p.sigE = 4;
    eA_kernel<<<eb + mb, 256, SMEM_SZ>>>(p);
  }
  // ---- e1 edges + f tail ----
  {
    P p = base;
    p.wp = wp1; p.wpNext = wp0;
    p.Wd1 = Wd1 + DCH * 2; p.bd1 = bd1 + DCH;
    p.gnd2_w = gnd2w + DCH; p.gnd2_b = gnd2b + DCH;
    p.gnc1_w = gnc1w + DCH; p.gnc1_b = gnc1b + DCH;
    p.nc = nc1;
    // f params (L1)
    p.agts = agts1;                                  // residual
    p.gnn_w = gnnw + DCH; p.gnn_b = gnnb + DCH;
    p.gnl_w = gnlw + DCH; p.gnl_b = gnlb + DCH;
    p.out = (float*)d_out;
    p.sigE = 5;
    eB_kernel<<<eb + mb, 256, SMEM_SZ>>>(p);
  }
}